// round 2
// baseline (speedup 1.0000x reference)
#include <cuda_runtime.h>
#include <cstdint>

// Problem constants
#define B_   1024
#define T_   200
#define H_   128
#define G_   384      // 3*H
#define ROWS 8        // batch rows per CTA
#define NCTA 128      // B_/ROWS
#define NTHR 384      // one thread per gate index

typedef unsigned long long ull;

// ---- packed f32x2 helpers (ptxas will not auto-fuse; must be PTX) ----
__device__ __forceinline__ ull pack2(float a, float b) {
    ull r; asm("mov.b64 %0,{%1,%2};" : "=l"(r) : "f"(a), "f"(b)); return r;
}
__device__ __forceinline__ void fma2(ull& c, ull a, ull b) {
    asm("fma.rn.f32x2 %0,%1,%2,%0;" : "+l"(c) : "l"(a), "l"(b));
}
__device__ __forceinline__ float2 unpack2(ull v) {
    float lo, hi; asm("mov.b64 {%0,%1},%2;" : "=f"(lo), "=f"(hi) : "l"(v));
    return make_float2(lo, hi);
}

__device__ __forceinline__ float sigmoid_fast(float x) {
    // 1/(1+e^-x); __expf(inf)->inf -> 0, __expf(-inf)->0 -> 1. Safe.
    return 1.0f / (1.0f + __expf(-x));
}
__device__ __forceinline__ float tanh_fast(float x) {
    float ax = fabsf(x);
    float e  = __expf(-2.0f * ax);          // e in [0,1]
    float t  = __fdividef(1.0f - e, 1.0f + e);
    return copysignf(t, x);
}

// Dual matvec: gi[r] = bi + dot(Wih_row_j, x_row_r), gh[r] = bh + dot(Whh_row_j, h_row_r)
// Accumulators pack (even-k sum, odd-k sum); weight pairs come directly from float4 loads.
__device__ __forceinline__ void mv2(const float* __restrict__ sx,
                                    const float* __restrict__ sh,
                                    const float4* __restrict__ wi4,
                                    const float4* __restrict__ wh4,
                                    float bi, float bh,
                                    float* gi, float* gh) {
    ull ai[ROWS], ah[ROWS];
#pragma unroll
    for (int r = 0; r < ROWS; r++) { ai[r] = pack2(bi, 0.0f); ah[r] = pack2(bh, 0.0f); }
#pragma unroll 4
    for (int k4 = 0; k4 < H_ / 4; k4++) {
        float4 wiv = __ldg(wi4 + k4);
        float4 whv = __ldg(wh4 + k4);
        ull wi0 = pack2(wiv.x, wiv.y), wi1 = pack2(wiv.z, wiv.w);
        ull wh0 = pack2(whv.x, whv.y), wh1 = pack2(whv.z, whv.w);
#pragma unroll
        for (int r = 0; r < ROWS; r++) {
            ulonglong2 xv = *(const ulonglong2*)(sx + r * H_ + k4 * 4);
            fma2(ai[r], wi0, xv.x);
            fma2(ai[r], wi1, xv.y);
            ulonglong2 hv = *(const ulonglong2*)(sh + r * H_ + k4 * 4);
            fma2(ah[r], wh0, hv.x);
            fma2(ah[r], wh1, hv.y);
        }
    }
#pragma unroll
    for (int r = 0; r < ROWS; r++) {
        float2 a = unpack2(ai[r]); gi[r] = a.x + a.y;
        float2 b = unpack2(ah[r]); gh[r] = b.x + b.y;
    }
}

__global__ void __launch_bounds__(NTHR, 1)
gru_kernel(const int* __restrict__ il,
           const float* __restrict__ mask,
           const float* __restrict__ emb,
           const float* __restrict__ Wih,
           const float* __restrict__ Whh,
           const float* __restrict__ bih,
           const float* __restrict__ bhh,
           const float* __restrict__ h2o_w,
           const float* __restrict__ h2o_b,
           float* __restrict__ out1,     // (B,199,H)
           float* __restrict__ out4)     // (B,200,2H)
{
    __shared__ __align__(16) float sx [ROWS * H_];   // current layer input / h2o input
    __shared__ __align__(16) float sh0[ROWS * H_];   // hidden layer 0
    __shared__ __align__(16) float sh1[ROWS * H_];   // hidden layer 1
    __shared__ __align__(16) float sg [ROWS * G_];   // gate pre/post-activations
    __shared__ __align__(16) float shn[ROWS * H_];   // hn (gh n-slice)
    __shared__ float skeep[ROWS];

    const int j  = threadIdx.x;            // gate index 0..383
    const int b0 = blockIdx.x * ROWS;

    // zero hidden state
    for (int i = j; i < ROWS * H_; i += NTHR) { sh0[i] = 0.0f; sh1[i] = 0.0f; }

    // per-thread persistent weights/bias pointers
    const float bi0 = bih[j],        bh0 = bhh[j];
    const float bi1 = bih[G_ + j],   bh1 = bhh[G_ + j];
    const float4* wi0 = (const float4*)Wih + j * (H_ / 4);
    const float4* wh0 = (const float4*)Whh + j * (H_ / 4);
    const float4* wi1 = (const float4*)(Wih + G_ * H_) + j * (H_ / 4);
    const float4* wh1 = (const float4*)(Whh + G_ * H_) + j * (H_ / 4);
    const int   hi  = j & (H_ - 1);     // h2o output index for tid<256
    const int   hhalf = j >> 7;         // row-half for h2o
    const float ob  = (j < 256) ? h2o_b[hi] : 0.0f;
    const float4* wo4 = (const float4*)h2o_w + hi * (H_ / 4);

    __syncthreads();

    for (int t = 0; t < T_; t++) {
        // ---- load x = emb[il[b,t]] into sx[row][k], write out4 low half ----
        if (j < 256) {
            int row = j >> 5;
            int k4  = j & 31;
            int tok = il[(b0 + row) * T_ + t];
            float4 v = __ldg((const float4*)emb + (size_t)tok * 32 + k4);
            *(float4*)(sx + row * H_ + k4 * 4) = v;
            *(float4*)(out4 + ((size_t)(b0 + row) * T_ + t) * 256 + k4 * 4) = v;
        }
        if (j < ROWS) {
            float m = mask[(b0 + j) * T_ + t];
            skeep[j] = (m != 0.0f) ? 1.0f : 0.0f;
        }
        __syncthreads();

        // ================= layer 0 =================
        {
            float gi[ROWS], gh[ROWS];
            mv2(sx, sh0, wi0, wh0, bi0, bh0, gi, gh);
            if (j < 2 * H_) {
#pragma unroll
                for (int r = 0; r < ROWS; r++)
                    sg[r * G_ + j] = sigmoid_fast(gi[r] + gh[r]);
            } else {
#pragma unroll
                for (int r = 0; r < ROWS; r++) {
                    sg[r * G_ + j]          = gi[r];        // inn
                    shn[r * H_ + (j - 256)] = gh[r];        // hn
                }
            }
            __syncthreads();
            if (j < H_) {
#pragma unroll
                for (int r = 0; r < ROWS; r++) {
                    float rv  = sg[r * G_ + j];
                    float zv  = sg[r * G_ + H_ + j];
                    float inn = sg[r * G_ + 2 * H_ + j];
                    float hn  = shn[r * H_ + j];
                    float nv  = tanh_fast(fmaf(rv, hn, inn));
                    float ho  = sh0[r * H_ + j];
                    float hnew = fmaf(zv, ho - nv, nv);
                    sx [r * H_ + j] = hnew;                 // input to layer 1 (unmasked)
                    sh0[r * H_ + j] = hnew * skeep[r];      // masked hidden
                }
            }
            __syncthreads();
        }

        // ================= layer 1 =================
        {
            float gi[ROWS], gh[ROWS];
            mv2(sx, sh1, wi1, wh1, bi1, bh1, gi, gh);
            if (j < 2 * H_) {
#pragma unroll
                for (int r = 0; r < ROWS; r++)
                    sg[r * G_ + j] = sigmoid_fast(gi[r] + gh[r]);
            } else {
#pragma unroll
                for (int r = 0; r < ROWS; r++) {
                    sg[r * G_ + j]          = gi[r];
                    shn[r * H_ + (j - 256)] = gh[r];
                }
            }
            __syncthreads();
            if (j < H_) {
#pragma unroll
                for (int r = 0; r < ROWS; r++) {
                    float rv  = sg[r * G_ + j];
                    float zv  = sg[r * G_ + H_ + j];
                    float inn = sg[r * G_ + 2 * H_ + j];
                    float hn  = shn[r * H_ + j];
                    float nv  = tanh_fast(fmaf(rv, hn, inn));
                    float ho  = sh1[r * H_ + j];
                    float hnew = fmaf(zv, ho - nv, nv);
                    sx [r * H_ + j] = hnew;                 // input to h2o (unmasked)
                    sh1[r * H_ + j] = hnew * skeep[r];
                }
            }
            __syncthreads();
        }

        // ================= h2o: out = tanh(h1 @ h2o_w.T + b) =================
        if (j < 256) {
            ull acc[4];
#pragma unroll
            for (int rr = 0; rr < 4; rr++) acc[rr] = pack2(ob, 0.0f);
#pragma unroll 4
            for (int k4 = 0; k4 < H_ / 4; k4++) {
                float4 wv = __ldg(wo4 + k4);
                ull w0 = pack2(wv.x, wv.y), w1 = pack2(wv.z, wv.w);
#pragma unroll
                for (int rr = 0; rr < 4; rr++) {
                    ulonglong2 xv = *(const ulonglong2*)(sx + (hhalf * 4 + rr) * H_ + k4 * 4);
                    fma2(acc[rr], w0, xv.x);
                    fma2(acc[rr], w1, xv.y);
                }
            }
#pragma unroll
            for (int rr = 0; rr < 4; rr++) {
                float2 s = unpack2(acc[rr]);
                float o  = tanh_fast(s.x + s.y);
                size_t gb = (size_t)(b0 + hhalf * 4 + rr);
                out4[(gb * T_ + t) * 256 + H_ + hi] = o;
                if (t < T_ - 1)
                    out1[(gb * (T_ - 1) + t) * H_ + hi] = o;
            }
        }
        __syncthreads();  // protect sx before next step's x-load
    }
}

// out2[b,t,:] = emb[il[b,t+1]];  out3[b,t,:] = emb[neg[b,t]]   (t in [0,199))
__global__ void gather_kernel(const int* __restrict__ il,
                              const int* __restrict__ neg,
                              const float4* __restrict__ emb4,
                              float4* __restrict__ out2,
                              float4* __restrict__ out3)
{
    int idx = blockIdx.x * blockDim.x + threadIdx.x;
    const int n4 = B_ * (T_ - 1) * (H_ / 4);
    if (idx >= n4) return;
    int k4 = idx & 31;
    int bt = idx >> 5;                // b*(T-1) + t
    int b  = bt / (T_ - 1);
    int t  = bt - b * (T_ - 1);
    int p  = il [b * T_ + t + 1];
    int q  = neg[b * T_ + t];
    out2[idx] = __ldg(emb4 + (size_t)p * 32 + k4);
    out3[idx] = __ldg(emb4 + (size_t)q * 32 + k4);
}

extern "C" void kernel_launch(void* const* d_in, const int* in_sizes, int n_in,
                              void* d_out, int out_size)
{
    const int*   il    = (const int*)  d_in[0];
    const float* mask  = (const float*)d_in[1];
    const int*   neg   = (const int*)  d_in[2];
    const float* emb   = (const float*)d_in[3];
    const float* Wih   = (const float*)d_in[4];
    const float* Whh   = (const float*)d_in[5];
    const float* bih   = (const float*)d_in[6];
    const float* bhh   = (const float*)d_in[7];
    const float* h2o_w = (const float*)d_in[8];
    const float* h2o_b = (const float*)d_in[9];

    float* out  = (float*)d_out;
    float* out1 = out;
    float* out2 = out1 + (size_t)B_ * (T_ - 1) * H_;
    float* out3 = out2 + (size_t)B_ * (T_ - 1) * H_;
    float* out4 = out3 + (size_t)B_ * (T_ - 1) * H_;

    const int n4 = B_ * (T_ - 1) * (H_ / 4);
    gather_kernel<<<(n4 + 255) / 256, 256>>>(il, neg, (const float4*)emb,
                                             (float4*)out2, (float4*)out3);
    gru_kernel<<<NCTA, NTHR>>>(il, mask, emb, Wih, Whh, bih, bhh,
                               h2o_w, h2o_b, out1, out4);
}

// round 3
// speedup vs baseline: 2.1014x; 2.1014x over previous
#include <cuda_runtime.h>
#include <cstdint>

// Problem constants
#define B_   1024
#define T_   200
#define H_   128
#define G_   384      // 3*H
#define ROWS 8        // batch rows per CTA
#define NCTA 128      // B_/ROWS
#define NTHR 384      // one thread per gate index
#define KPAD 12       // padded row stride (floats) for [k][row] SMEM layout

#define H2O_OFF (2*2*128*384)
__device__ float g_WT[2*2*128*384 + 128*128];   // transposed weights (852 KB scratch)

typedef unsigned long long ull;

// ---- packed f32x2 helpers ----
__device__ __forceinline__ ull pack2(float a, float b) {
    ull r; asm("mov.b64 %0,{%1,%2};" : "=l"(r) : "f"(a), "f"(b)); return r;
}
__device__ __forceinline__ void fma2(ull& c, ull a, ull b) {
    asm("fma.rn.f32x2 %0,%1,%2,%0;" : "+l"(c) : "l"(a), "l"(b));
}
__device__ __forceinline__ float2 unpack2(ull v) {
    float lo, hi; asm("mov.b64 {%0,%1},%2;" : "=f"(lo), "=f"(hi) : "l"(v));
    return make_float2(lo, hi);
}

__device__ __forceinline__ float sigmoid_fast(float x) {
    return 1.0f / (1.0f + __expf(-x));
}
__device__ __forceinline__ float tanh_fast(float x) {
    float ax = fabsf(x);
    float e  = __expf(-2.0f * ax);
    float t  = __fdividef(1.0f - e, 1.0f + e);
    return copysignf(t, x);
}

// One-time weight transpose:  WT[((l*2+m)*128 + k)*384 + j] = W_m[l][j][k]
__global__ void prep_kernel(const float* __restrict__ Wih,
                            const float* __restrict__ Whh,
                            const float* __restrict__ h2o_w)
{
    int idx = blockIdx.x * blockDim.x + threadIdx.x;
    const int NW = 2 * 128 * 384;          // per matrix family (2 layers)
    if (idx < NW) {
        int j = idx % G_;
        int rest = idx / G_;
        int k = rest % H_;
        int l = rest / H_;
        g_WT[((l*2 + 0)*H_ + k)*G_ + j] = Wih[(l*G_ + j)*H_ + k];
        g_WT[((l*2 + 1)*H_ + k)*G_ + j] = Whh[(l*G_ + j)*H_ + k];
    } else if (idx < NW + H_*H_) {
        int i2 = idx - NW;
        int oi = i2 % H_;
        int k  = i2 / H_;
        g_WT[H2O_OFF + k*H_ + oi] = h2o_w[oi*H_ + k];
    }
}

// Dual matvec over transposed weights: thread j accumulates gate j for 8 rows.
// gi[r] = bi + dot(Wih[j,:], x[r,:]);  gh[r] = bh + dot(Whh[j,:], h[r,:])
__device__ __forceinline__ void dualmv(const float* __restrict__ xT,
                                       const float* __restrict__ hT,
                                       const float* __restrict__ wi,
                                       const float* __restrict__ wh,
                                       float bi, float bh,
                                       float* gi, float* gh)
{
    ull ai[4], ah[4];
#pragma unroll
    for (int p = 0; p < 4; p++) { ai[p] = pack2(bi, bi); ah[p] = pack2(bh, bh); }
#pragma unroll 8
    for (int k = 0; k < H_; k++) {
        float wiv = __ldg(wi + k * G_);          // coalesced: lanes j contiguous
        float whv = __ldg(wh + k * G_);
        ull wi2 = pack2(wiv, wiv);
        ull wh2 = pack2(whv, whv);
        ulonglong2 x01 = *(const ulonglong2*)(xT + k * KPAD);      // rows 0-3 (bcast)
        ulonglong2 x23 = *(const ulonglong2*)(xT + k * KPAD + 4);  // rows 4-7
        ulonglong2 h01 = *(const ulonglong2*)(hT + k * KPAD);
        ulonglong2 h23 = *(const ulonglong2*)(hT + k * KPAD + 4);
        fma2(ai[0], wi2, x01.x); fma2(ai[1], wi2, x01.y);
        fma2(ai[2], wi2, x23.x); fma2(ai[3], wi2, x23.y);
        fma2(ah[0], wh2, h01.x); fma2(ah[1], wh2, h01.y);
        fma2(ah[2], wh2, h23.x); fma2(ah[3], wh2, h23.y);
    }
#pragma unroll
    for (int p = 0; p < 4; p++) {
        float2 a = unpack2(ai[p]); gi[2*p] = a.x; gi[2*p+1] = a.y;
        float2 b = unpack2(ah[p]); gh[2*p] = b.x; gh[2*p+1] = b.y;
    }
}

__global__ void __launch_bounds__(NTHR, 1)
gru_kernel(const int* __restrict__ il,
           const float* __restrict__ mask,
           const float* __restrict__ emb,
           const float* __restrict__ bih,
           const float* __restrict__ bhh,
           const float* __restrict__ h2o_b,
           float* __restrict__ out1,     // (B,199,H)
           float* __restrict__ out4)     // (B,200,2H)
{
    __shared__ __align__(16) float bufA[H_ * KPAD];   // x input / layer1 output
    __shared__ __align__(16) float bufB[H_ * KPAD];   // layer0 output
    __shared__ __align__(16) float h0T [H_ * KPAD];
    __shared__ __align__(16) float h1T [H_ * KPAD];
    __shared__ __align__(16) float sg  [ROWS * G_];   // gate values [r][j]
    __shared__ __align__(16) float shn [ROWS * H_];   // hn slice    [r][j]
    __shared__ float skeep[ROWS];

    const int j  = threadIdx.x;
    const int b0 = blockIdx.x * ROWS;

    for (int i = j; i < H_ * KPAD; i += NTHR) { h0T[i] = 0.0f; h1T[i] = 0.0f; }

    const float bi0 = bih[j],      bh0 = bhh[j];
    const float bi1 = bih[G_ + j], bh1 = bhh[G_ + j];
    const float* wi0 = g_WT + 0 * 128 * 384 + j;
    const float* wh0 = g_WT + 1 * 128 * 384 + j;
    const float* wi1 = g_WT + 2 * 128 * 384 + j;
    const float* wh1 = g_WT + 3 * 128 * 384 + j;

    const int   oi   = j & (H_ - 1);
    const int   half = (j >> 7) & 1;           // row half for h2o (4 rows each)
    const float ob   = (j < 256) ? h2o_b[oi] : 0.0f;
    const float* wo  = g_WT + H2O_OFF + oi;

    const int lr  = j & 7;                      // loader: row
    const int lk4 = j >> 3;                     // loader: k-quad

    __syncthreads();

    for (int t = 0; t < T_; t++) {
        // ---- load x = emb[il[b,t]] into bufA[k][r] transposed; write out4 low half ----
        if (j < 256) {
            int tok = il[(b0 + lr) * T_ + t];
            float4 v = __ldg((const float4*)emb + (size_t)tok * 32 + lk4);
            bufA[(4*lk4 + 0) * KPAD + lr] = v.x;
            bufA[(4*lk4 + 1) * KPAD + lr] = v.y;
            bufA[(4*lk4 + 2) * KPAD + lr] = v.z;
            bufA[(4*lk4 + 3) * KPAD + lr] = v.w;
            ((float4*)(out4 + ((size_t)(b0 + lr) * T_ + t) * 256))[lk4] = v;
        }
        if (j < ROWS) {
            float m = mask[(b0 + j) * T_ + t];
            skeep[j] = (m != 0.0f) ? 1.0f : 0.0f;
        }
        __syncthreads();

        // ================= layer 0 =================
        {
            float gi[ROWS], gh[ROWS];
            dualmv(bufA, h0T, wi0, wh0, bi0, bh0, gi, gh);
            if (j < 2 * H_) {
#pragma unroll
                for (int r = 0; r < ROWS; r++)
                    sg[r * G_ + j] = sigmoid_fast(gi[r] + gh[r]);
            } else {
#pragma unroll
                for (int r = 0; r < ROWS; r++) {
                    sg [r * G_ + j]         = gi[r];        // inn (+bias)
                    shn[r * H_ + (j - 256)] = gh[r];        // hn  (+bias)
                }
            }
            __syncthreads();
            if (j < H_) {
                float hw[ROWS];
                float4 o0 = *(float4*)(h0T + j * KPAD);
                float4 o1 = *(float4*)(h0T + j * KPAD + 4);
                float hold[ROWS] = {o0.x,o0.y,o0.z,o0.w,o1.x,o1.y,o1.z,o1.w};
#pragma unroll
                for (int r = 0; r < ROWS; r++) {
                    float rv  = sg[r * G_ + j];
                    float zv  = sg[r * G_ + H_ + j];
                    float inn = sg[r * G_ + 2 * H_ + j];
                    float hn  = shn[r * H_ + j];
                    float nv  = tanh_fast(fmaf(rv, hn, inn));
                    hw[r] = fmaf(zv, hold[r] - nv, nv);
                }
                *(float4*)(bufB + j * KPAD)     = make_float4(hw[0],hw[1],hw[2],hw[3]);
                *(float4*)(bufB + j * KPAD + 4) = make_float4(hw[4],hw[5],hw[6],hw[7]);
                *(float4*)(h0T  + j * KPAD)     = make_float4(hw[0]*skeep[0],hw[1]*skeep[1],hw[2]*skeep[2],hw[3]*skeep[3]);
                *(float4*)(h0T  + j * KPAD + 4) = make_float4(hw[4]*skeep[4],hw[5]*skeep[5],hw[6]*skeep[6],hw[7]*skeep[7]);
            }
            __syncthreads();
        }

        // ================= layer 1 =================
        {
            float gi[ROWS], gh[ROWS];
            dualmv(bufB, h1T, wi1, wh1, bi1, bh1, gi, gh);
            if (j < 2 * H_) {
#pragma unroll
                for (int r = 0; r < ROWS; r++)
                    sg[r * G_ + j] = sigmoid_fast(gi[r] + gh[r]);
            } else {
#pragma unroll
                for (int r = 0; r < ROWS; r++) {
                    sg [r * G_ + j]         = gi[r];
                    shn[r * H_ + (j - 256)] = gh[r];
                }
            }
            __syncthreads();
            if (j < H_) {
                float hw[ROWS];
                float4 o0 = *(float4*)(h1T + j * KPAD);
                float4 o1 = *(float4*)(h1T + j * KPAD + 4);
                float hold[ROWS] = {o0.x,o0.y,o0.z,o0.w,o1.x,o1.y,o1.z,o1.w};
#pragma unroll
                for (int r = 0; r < ROWS; r++) {
                    float rv  = sg[r * G_ + j];
                    float zv  = sg[r * G_ + H_ + j];
                    float inn = sg[r * G_ + 2 * H_ + j];
                    float hn  = shn[r * H_ + j];
                    float nv  = tanh_fast(fmaf(rv, hn, inn));
                    hw[r] = fmaf(zv, hold[r] - nv, nv);
                }
                *(float4*)(bufA + j * KPAD)     = make_float4(hw[0],hw[1],hw[2],hw[3]);
                *(float4*)(bufA + j * KPAD + 4) = make_float4(hw[4],hw[5],hw[6],hw[7]);
                *(float4*)(h1T  + j * KPAD)     = make_float4(hw[0]*skeep[0],hw[1]*skeep[1],hw[2]*skeep[2],hw[3]*skeep[3]);
                *(float4*)(h1T  + j * KPAD + 4) = make_float4(hw[4]*skeep[4],hw[5]*skeep[5],hw[6]*skeep[6],hw[7]*skeep[7]);
            }
            __syncthreads();
        }

        // ================= h2o: out = tanh(h1 @ h2o_w.T + b) =================
        if (j < 256) {
            ull acc[2];
            acc[0] = pack2(ob, ob);
            acc[1] = pack2(ob, ob);
#pragma unroll 8
            for (int k = 0; k < H_; k++) {
                float w = __ldg(wo + k * H_);            // coalesced
                ull w2 = pack2(w, w);
                ulonglong2 xv = *(const ulonglong2*)(bufA + k * KPAD + 4 * half);
                fma2(acc[0], w2, xv.x);
                fma2(acc[1], w2, xv.y);
            }
#pragma unroll
            for (int p = 0; p < 2; p++) {
                float2 s = unpack2(acc[p]);
                int r0 = 4 * half + 2 * p;
                float o0 = tanh_fast(s.x);
                float o1 = tanh_fast(s.y);
                size_t gb0 = (size_t)(b0 + r0);
                size_t gb1 = (size_t)(b0 + r0 + 1);
                out4[(gb0 * T_ + t) * 256 + H_ + oi] = o0;
                out4[(gb1 * T_ + t) * 256 + H_ + oi] = o1;
                if (t < T_ - 1) {
                    out1[(gb0 * (T_ - 1) + t) * H_ + oi] = o0;
                    out1[(gb1 * (T_ - 1) + t) * H_ + oi] = o1;
                }
            }
        }
        __syncthreads();   // protect bufA before next step's x-load
    }
}

// out2[b,t,:] = emb[il[b,t+1]];  out3[b,t,:] = emb[neg[b,t]]
__global__ void gather_kernel(const int* __restrict__ il,
                              const int* __restrict__ neg,
                              const float4* __restrict__ emb4,
                              float4* __restrict__ out2,
                              float4* __restrict__ out3)
{
    int idx = blockIdx.x * blockDim.x + threadIdx.x;
    const int n4 = B_ * (T_ - 1) * (H_ / 4);
    if (idx >= n4) return;
    int k4 = idx & 31;
    int bt = idx >> 5;
    int b  = bt / (T_ - 1);
    int t  = bt - b * (T_ - 1);
    int p  = il [b * T_ + t + 1];
    int q  = neg[b * T_ + t];
    out2[idx] = __ldg(emb4 + (size_t)p * 32 + k4);
    out3[idx] = __ldg(emb4 + (size_t)q * 32 + k4);
}

extern "C" void kernel_launch(void* const* d_in, const int* in_sizes, int n_in,
                              void* d_out, int out_size)
{
    const int*   il    = (const int*)  d_in[0];
    const float* mask  = (const float*)d_in[1];
    const int*   neg   = (const int*)  d_in[2];
    const float* emb   = (const float*)d_in[3];
    const float* Wih   = (const float*)d_in[4];
    const float* Whh   = (const float*)d_in[5];
    const float* bih   = (const float*)d_in[6];
    const float* bhh   = (const float*)d_in[7];
    const float* h2o_w = (const float*)d_in[8];
    const float* h2o_b = (const float*)d_in[9];

    float* out  = (float*)d_out;
    float* out1 = out;
    float* out2 = out1 + (size_t)B_ * (T_ - 1) * H_;
    float* out3 = out2 + (size_t)B_ * (T_ - 1) * H_;
    float* out4 = out3 + (size_t)B_ * (T_ - 1) * H_;

    const int nprep = 2 * 128 * 384 + 128 * 128;
    prep_kernel<<<(nprep + 255) / 256, 256>>>(Wih, Whh, h2o_w);

    const int n4 = B_ * (T_ - 1) * (H_ / 4);
    gather_kernel<<<(n4 + 255) / 256, 256>>>(il, neg, (const float4*)emb,
                                             (float4*)out2, (float4*)out3);

    gru_kernel<<<NCTA, NTHR>>>(il, mask, emb, bih, bhh, h2o_b, out1, out4);
}